// round 5
// baseline (speedup 1.0000x reference)
#include <cuda_runtime.h>
#include <math.h>

#define D_DIM   10000
#define LVL     100
#define T_STEPS 2048
#define TERMS   2046          // T - 3 + 1
#define NCHUNK  27
#define TCHUNK  76            // 27*76 = 2052 >= 2046
#define NTILE   27            // 81 warps / 3 warps-per-block
#define TOTAL_BLKS (NTILE * NCHUNK)
#define TILE_W  400           // padded level-tile width (bytes)
#define WARPS_PB 3
#define THREADS_PB 96
#define EXT_W   10512         // D + 512, circularly extended & shifted by 4; %16==0
#define COMB_BLOCKS 79        // ceil(10000/128)
#define COMB_TPB 128
#define PREP_ELEMS (LVL * EXT_W)             // 1051200
#define PREP_BLOCKS ((PREP_ELEMS / 4 + COMB_TPB - 1) / COMB_TPB)   // 4 elems/thread

// ---------------- scratch (static device globals; no allocation) ----------------
__device__ unsigned char g_lwext[LVL * EXT_W];     // ext[row][j] = (LW[row][(j-4) mod D] > 0)
__device__ unsigned char g_keys01[4 * D_DIM];      // (keys_hv > 0)
__device__ int4          g_idx4[T_STEPS];          // per-t levels, pre-scaled by TILE_W
__device__ int           g_sum[D_DIM];             // exact integer accumulator
__device__ float         g_comb[D_DIM];
__device__ int           g_ctr;

__constant__ int c_CF[29] = {547,548,549,551,554,556,557,558,559,560,561,562,563,565,
                             566,567,570,576,580,581,582,583,584,585,588,593,598,599,600};

// ---------------- merged pre kernel: comb blocks first, then prep blocks ----------------
__device__ __forceinline__ int level_of(float x) {
    x = fminf(fmaxf(x, 0.0f), 1.0f);
    float r = rintf(x * 99.0f);          // round-half-to-even, matches jnp.round
    int i = (int)r;
    i = i < 0 ? 0 : (i > 99 ? 99 : i);
    return i;
}

__global__ __launch_bounds__(COMB_TPB) void k_pre(
        const float* __restrict__ signals,
        const float* __restrict__ keys,
        const float* __restrict__ lw,
        const float* __restrict__ feat,
        const float* __restrict__ feat_w,
        const float* __restrict__ feat_b,
        const float* __restrict__ mfcc_w,
        const float* __restrict__ mfcc_b) {
    int tid = threadIdx.x;
    if (blockIdx.x < COMB_BLOCKS) {
        // ---- comb: block owns 128 consecutive d; smem-staged coalesced matvec ----
        __shared__ __align__(16) float sh[COMB_TPB * 91 + 600];   // wtile + feat stage
        float* wtile  = sh;
        float* feat_s = sh + COMB_TPB * 91;

        int d0 = blockIdx.x * COMB_TPB;
        int d  = d0 + tid;
        int rows = D_DIM - d0; if (rows > COMB_TPB) rows = COMB_TPB;
        int nInt4 = (rows * 91) >> 2;       // rows*91 always divisible by 4 here

        for (int i = tid; i < 600; i += COMB_TPB) feat_s[i] = feat[i];

        float p[6];
        #pragma unroll
        for (int k = 0; k < 6; k++) {
            __syncthreads();
            const int4* src = (const int4*)(mfcc_w + ((size_t)(k * D_DIM + d0)) * 91);
            for (int i = tid; i < nInt4; i += COMB_TPB) ((int4*)wtile)[i] = src[i];
            __syncthreads();
            if (d < D_DIM) {
                const float* row = wtile + tid * 91;
                const float* fr  = feat_s + k * 91;
                float s = 0.0f;
                #pragma unroll
                for (int f = 0; f < 91; f++) s += row[f] * fr[f];
                p[k] = s;
            }
        }

        if (d < D_DIM) {
            float mfcc_hv = 1.0f;
            #pragma unroll
            for (int k = 0; k < 6; k++) {
                float b = mfcc_b[k * D_DIM + d];
                mfcc_hv *= cosf(p[k] + b) * sinf(p[k]);
            }
            float h[29];
            #pragma unroll
            for (int j = 0; j < 29; j++) {
                float sel  = feat_s[c_CF[j] - 1];
                float wv   = feat_w[j * D_DIM + d];
                float bv   = feat_b[j * D_DIM + d];
                float proj = sel * wv;
                h[j] = cosf(proj + bv) * sinf(proj);
            }
            float comb =
                  h[0]  * h[8]  * h[13]
                + h[1]  * h[9]  * h[14]
                + h[2]  * h[10] * h[15]
                + h[3]  * h[4]
                + h[5] * h[7] * h[22] * h[6] * h[23] * h[19] * h[18]
                       * h[20] * h[21] * h[26] * h[28] * h[27]
                + h[11] + h[12]
                + h[16] * h[24]
                + h[17] + h[25]
                + mfcc_hv;
            g_comb[d] = comb;
        }
    } else {
        // ---- prep: 4 elements per thread ----
        int gi = (blockIdx.x - COMB_BLOCKS) * COMB_TPB + tid;
        int e0 = 4 * gi;
        if (e0 < PREP_ELEMS) {
            int row  = e0 / EXT_W;
            int col0 = e0 - row * EXT_W;          // EXT_W%4==0 so all 4 in same row
            uchar4 v;
            unsigned char* pv = (unsigned char*)&v;
            #pragma unroll
            for (int j = 0; j < 4; j++) {
                int src = col0 + j - 4;
                if (src < 0) src += D_DIM;
                else if (src >= D_DIM) src -= D_DIM;
                pv[j] = (lw[row * D_DIM + src] > 0.0f) ? 1 : 0;
            }
            *(uchar4*)(g_lwext + e0) = v;
        }
        if (gi < D_DIM) {                          // keys: 4*D bytes, gi<10000
            uchar4 v;
            unsigned char* pv = (unsigned char*)&v;
            #pragma unroll
            for (int j = 0; j < 4; j++) pv[j] = (keys[e0 + j] > 0.0f) ? 1 : 0;
            *(uchar4*)(g_keys01 + e0) = v;
            g_sum[gi] = 0;
        }
        if (gi < T_STEPS) {
            float4 sg = ((const float4*)signals)[gi];
            g_idx4[gi] = make_int4(level_of(sg.x) * TILE_W, level_of(sg.y) * TILE_W,
                                   level_of(sg.z) * TILE_W, level_of(sg.w) * TILE_W);
        }
        if (gi == 0) g_ctr = 0;
    }
}

// ---------------- main n-gram kernel (+ fused final) ----------------
// Bytewise sign algebra: b01 = (x>0); lw*key = 1-2*(bl^bk); per_t = 4-2*s, s=sum_c xor.
// With u = s-2, per_t = -2u, so ngram term = -8 * uA*uB*uC. All exact integers.
__device__ __forceinline__ void load_u(const unsigned char* lp, const int4 iq,
                                       int kw0, int kw1, int kw2, int kw3, int* u) {
    int x0 = *(const int*)(lp + iq.x) ^ kw0;
    int x1 = *(const int*)(lp + iq.y) ^ kw1;
    int x2 = *(const int*)(lp + iq.z) ^ kw2;
    int x3 = *(const int*)(lp + iq.w) ^ kw3;
    int sp = x0 + x1 + x2 + x3;       // bytewise sums, each <= 4, no carries
    u[0] = ( sp        & 0xFF) - 2;
    u[1] = ((sp >> 8 ) & 0xFF) - 2;
    u[2] = ((sp >> 16) & 0xFF) - 2;
    u[3] = ( sp >> 24        ) - 2;
}

__global__ __launch_bounds__(THREADS_PB) void k_main(float* __restrict__ out) {
    __shared__ unsigned char lw_sm[LVL * TILE_W];   // 40000 B
    __shared__ int4 idx_sm[TCHUNK + 2];
    __shared__ int s_last;

    int tb = blockIdx.x;     // column tile
    int s  = blockIdx.y;     // t-chunk
    int tid = threadIdx.x;
    int w = tid >> 5, l = tid & 31;

    // Load level tile, 16B vectorized (base2 aligned, ofs = skew within tile)
    int base  = 372 * tb;    // into ext array (already shifted by 4)
    int ofs   = base & 15;
    int base2 = base - ofs;
    {
        int4* dst = (int4*)lw_sm;
        #pragma unroll 4
        for (int i = tid; i < LVL * (TILE_W / 16); i += THREADS_PB) {
            int row = i / (TILE_W / 16);
            int c   = i - row * (TILE_W / 16);
            dst[i] = *(const int4*)(g_lwext + row * EXT_W + base2 + 16 * c);
        }
    }
    int ts = s * TCHUNK;
    int te = ts + TCHUNK; if (te > TERMS) te = TERMS;
    int nt = te - ts;                      // #terms this chunk (>= 1)
    for (int i = tid; i < nt + 2; i += THREADS_PB) idx_sm[i] = g_idx4[ts + i];
    __syncthreads();

    int g = WARPS_PB * tb + w;             // global warp id (column group)
    // this lane's 4 stream columns start at real col (124g - 4 + 4l) mod D
    int v = 124 * g - 4 + 4 * l;
    if (v < 0) v += D_DIM;
    if (v >= D_DIM) v -= D_DIM;
    int kw0 = *(const int*)(g_keys01 + 0 * D_DIM + v);
    int kw1 = *(const int*)(g_keys01 + 1 * D_DIM + v);
    int kw2 = *(const int*)(g_keys01 + 2 * D_DIM + v);
    int kw3 = *(const int*)(g_keys01 + 3 * D_DIM + v);

    const unsigned char* lp = lw_sm + (ofs + 124 * w + 4 * l);

    int p1[4], p2[4], cur[4];
    int acc[4] = {0, 0, 0, 0};
    load_u(lp, idx_sm[0], kw0, kw1, kw2, kw3, p2);   // u(ts)
    load_u(lp, idx_sm[1], kw0, kw1, kw2, kw3, p1);   // u(ts+1)

    #pragma unroll 3
    for (int i = 2; i < nt + 2; i++) {
        load_u(lp, idx_sm[i], kw0, kw1, kw2, kw3, cur);   // u(ts+i)
        // emit term(ts+i-2): u_{c-2}(t) * u_{c-1}(t+1) * u_c(t+2)
        int a0 = __shfl_up_sync(0xffffffffu, p2[2], 1);
        int a1 = __shfl_up_sync(0xffffffffu, p2[3], 1);
        int b0 = __shfl_up_sync(0xffffffffu, p1[3], 1);
        acc[0] += a0    * b0    * cur[0];
        acc[1] += a1    * p1[0] * cur[1];
        acc[2] += p2[0] * p1[1] * cur[2];
        acc[3] += p2[1] * p1[2] * cur[3];
        p2[0] = p1[0]; p2[1] = p1[1]; p2[2] = p1[2]; p2[3] = p1[3];
        p1[0] = cur[0]; p1[1] = cur[1]; p1[2] = cur[2]; p1[3] = cur[3];
    }

    if (l >= 1) {                           // lane 0 is halo-only
        int obase = 124 * g + 4 * (l - 1);
        #pragma unroll
        for (int j = 0; j < 4; j++) {
            int oc = obase + j;
            if (oc < D_DIM) atomicAdd(&g_sum[oc], acc[j]);   // exact int, order-free
        }
    }

    // ---- fused final: last block to finish quantizes the output ----
    __threadfence();
    __syncthreads();
    if (tid == 0) s_last = atomicAdd(&g_ctr, 1);
    __syncthreads();
    if (s_last == TOTAL_BLKS - 1) {
        __threadfence();
        for (int d = tid; d < D_DIM; d += THREADS_PB) {
            float sample = -8.0f * (float)g_sum[d];     // exact: |.| < 2^24
            float x = sample * g_comb[d];
            out[d] = (x > 0.0f) ? 1.0f : -1.0f;
        }
    }
}

// ---------------- launch ----------------
extern "C" void kernel_launch(void* const* d_in, const int* in_sizes, int n_in,
                              void* d_out, int out_size) {
    const float* signals = (const float*)d_in[0];
    const float* feat    = (const float*)d_in[1];
    const float* keys_hv = (const float*)d_in[2];
    const float* lw      = (const float*)d_in[3];
    const float* feat_w  = (const float*)d_in[4];
    const float* feat_b  = (const float*)d_in[5];
    const float* mfcc_w  = (const float*)d_in[6];
    const float* mfcc_b  = (const float*)d_in[7];
    float* out = (float*)d_out;

    k_pre  <<<COMB_BLOCKS + PREP_BLOCKS, COMB_TPB>>>(signals, keys_hv, lw,
                                                     feat, feat_w, feat_b, mfcc_w, mfcc_b);
    k_main <<<dim3(NTILE, NCHUNK), THREADS_PB>>>(out);
}

// round 6
// speedup vs baseline: 1.1689x; 1.1689x over previous
#include <cuda_runtime.h>
#include <math.h>

#define D_DIM   10000
#define LVL     100
#define T_STEPS 2048
#define TERMS   2046          // T - 3 + 1
#define NCHUNK  27
#define TCHUNK  76            // 27*76 = 2052 >= 2046
#define NTILE   27            // 81 warps / 3 warps-per-block
#define TILE_W  400           // padded level-tile width (bytes)
#define WARPS_PB 3
#define THREADS_PB 96
#define EXT_W   10512         // D + 512, circularly extended & shifted by 4; %16==0
#define PART_STRIDE 10048
#define COMB_BLOCKS 79        // ceil(10000/128)
#define COMB_TPB 128
#define PREP_ELEMS (LVL * EXT_W)             // 1051200
#define PREP_BLOCKS ((PREP_ELEMS / 4 + COMB_TPB - 1) / COMB_TPB)   // 4 elems/thread

// ---------------- scratch (static device globals; no allocation) ----------------
__device__ unsigned char g_lwext[LVL * EXT_W];     // ext[row][j] = (LW[row][(j-4) mod D] > 0)
__device__ unsigned char g_keys01[4 * D_DIM];      // (keys_hv > 0)
__device__ int4          g_idx4[T_STEPS];          // per-t levels, pre-scaled by TILE_W
__device__ int           g_partial[NCHUNK * PART_STRIDE];
__device__ float         g_comb[D_DIM];

__constant__ int c_CF[29] = {547,548,549,551,554,556,557,558,559,560,561,562,563,565,
                             566,567,570,576,580,581,582,583,584,585,588,593,598,599,600};

// ---------------- merged pre kernel: comb blocks first, then prep blocks ----------------
__device__ __forceinline__ int level_of(float x) {
    x = fminf(fmaxf(x, 0.0f), 1.0f);
    float r = rintf(x * 99.0f);          // round-half-to-even, matches jnp.round
    int i = (int)r;
    i = i < 0 ? 0 : (i > 99 ? 99 : i);
    return i;
}

__global__ __launch_bounds__(COMB_TPB) void k_pre(
        const float* __restrict__ signals,
        const float* __restrict__ keys,
        const float* __restrict__ lw,
        const float* __restrict__ feat,
        const float* __restrict__ feat_w,
        const float* __restrict__ feat_b,
        const float* __restrict__ mfcc_w,
        const float* __restrict__ mfcc_b) {
    int tid = threadIdx.x;
    if (blockIdx.x < COMB_BLOCKS) {
        // ---- comb: block owns 128 consecutive d; smem-staged coalesced matvec ----
        __shared__ __align__(16) float sh[COMB_TPB * 91 + 600];   // wtile + feat stage
        float* wtile  = sh;
        float* feat_s = sh + COMB_TPB * 91;

        int d0 = blockIdx.x * COMB_TPB;
        int d  = d0 + tid;
        int rows = D_DIM - d0; if (rows > COMB_TPB) rows = COMB_TPB;
        int nInt4 = (rows * 91) >> 2;       // rows*91 divisible by 4 for all tiles here

        for (int i = tid; i < 600; i += COMB_TPB) feat_s[i] = feat[i];

        float p[6];
        #pragma unroll
        for (int k = 0; k < 6; k++) {
            __syncthreads();
            const int4* src = (const int4*)(mfcc_w + ((size_t)(k * D_DIM + d0)) * 91);
            for (int i = tid; i < nInt4; i += COMB_TPB) ((int4*)wtile)[i] = src[i];
            __syncthreads();
            if (d < D_DIM) {
                const float* row = wtile + tid * 91;
                const float* fr  = feat_s + k * 91;
                float s = 0.0f;
                #pragma unroll
                for (int f = 0; f < 91; f++) s += row[f] * fr[f];
                p[k] = s;
            }
        }

        if (d < D_DIM) {
            float mfcc_hv = 1.0f;
            #pragma unroll
            for (int k = 0; k < 6; k++) {
                float b = mfcc_b[k * D_DIM + d];
                mfcc_hv *= cosf(p[k] + b) * sinf(p[k]);
            }
            float h[29];
            #pragma unroll
            for (int j = 0; j < 29; j++) {
                float sel  = feat_s[c_CF[j] - 1];
                float wv   = feat_w[j * D_DIM + d];
                float bv   = feat_b[j * D_DIM + d];
                float proj = sel * wv;
                h[j] = cosf(proj + bv) * sinf(proj);
            }
            float comb =
                  h[0]  * h[8]  * h[13]
                + h[1]  * h[9]  * h[14]
                + h[2]  * h[10] * h[15]
                + h[3]  * h[4]
                + h[5] * h[7] * h[22] * h[6] * h[23] * h[19] * h[18]
                       * h[20] * h[21] * h[26] * h[28] * h[27]
                + h[11] + h[12]
                + h[16] * h[24]
                + h[17] + h[25]
                + mfcc_hv;
            g_comb[d] = comb;
        }
    } else {
        // ---- prep: 4 elements per thread ----
        int gi = (blockIdx.x - COMB_BLOCKS) * COMB_TPB + tid;
        int e0 = 4 * gi;
        if (e0 < PREP_ELEMS) {
            int row  = e0 / EXT_W;
            int col0 = e0 - row * EXT_W;          // EXT_W%4==0 so all 4 in same row
            uchar4 v;
            unsigned char* pv = (unsigned char*)&v;
            #pragma unroll
            for (int j = 0; j < 4; j++) {
                int src = col0 + j - 4;
                if (src < 0) src += D_DIM;
                else if (src >= D_DIM) src -= D_DIM;
                pv[j] = (lw[row * D_DIM + src] > 0.0f) ? 1 : 0;
            }
            *(uchar4*)(g_lwext + e0) = v;
        }
        if (gi < D_DIM) {                          // keys: 4*D bytes
            uchar4 v;
            unsigned char* pv = (unsigned char*)&v;
            #pragma unroll
            for (int j = 0; j < 4; j++) pv[j] = (keys[e0 + j] > 0.0f) ? 1 : 0;
            *(uchar4*)(g_keys01 + e0) = v;
        }
        if (gi < T_STEPS) {
            float4 sg = ((const float4*)signals)[gi];
            g_idx4[gi] = make_int4(level_of(sg.x) * TILE_W, level_of(sg.y) * TILE_W,
                                   level_of(sg.z) * TILE_W, level_of(sg.w) * TILE_W);
        }
    }
}

// ---------------- main n-gram kernel ----------------
// Bytewise sign algebra: b01 = (x>0); lw*key = 1-2*(bl^bk); per_t = 4-2*s, s=sum_c xor.
// With u = s-2, per_t = -2u, so ngram term = -8 * uA*uB*uC. All exact integers.
__device__ __forceinline__ void load_u(const unsigned char* lp, const int4 iq,
                                       int kw0, int kw1, int kw2, int kw3, int* u) {
    int x0 = *(const int*)(lp + iq.x) ^ kw0;
    int x1 = *(const int*)(lp + iq.y) ^ kw1;
    int x2 = *(const int*)(lp + iq.z) ^ kw2;
    int x3 = *(const int*)(lp + iq.w) ^ kw3;
    int sp = x0 + x1 + x2 + x3;       // bytewise sums, each <= 4, no carries
    u[0] = ( sp        & 0xFF) - 2;
    u[1] = ((sp >> 8 ) & 0xFF) - 2;
    u[2] = ((sp >> 16) & 0xFF) - 2;
    u[3] = ( sp >> 24        ) - 2;
}

__global__ __launch_bounds__(THREADS_PB) void k_main() {
    __shared__ unsigned char lw_sm[LVL * TILE_W];   // 40000 B
    __shared__ int4 idx_sm[TCHUNK + 2];

    int tb = blockIdx.x;     // column tile
    int s  = blockIdx.y;     // t-chunk
    int tid = threadIdx.x;
    int w = tid >> 5, l = tid & 31;

    // Load level tile, 16B vectorized (base2 aligned, ofs = skew within tile)
    int base  = 372 * tb;    // into ext array (already shifted by 4)
    int ofs   = base & 15;
    int base2 = base - ofs;
    {
        int4* dst = (int4*)lw_sm;
        #pragma unroll 4
        for (int i = tid; i < LVL * (TILE_W / 16); i += THREADS_PB) {
            int row = i / (TILE_W / 16);
            int c   = i - row * (TILE_W / 16);
            dst[i] = *(const int4*)(g_lwext + row * EXT_W + base2 + 16 * c);
        }
    }
    int ts = s * TCHUNK;
    int te = ts + TCHUNK; if (te > TERMS) te = TERMS;
    int nt = te - ts;                      // #terms this chunk (>= 1)
    for (int i = tid; i < nt + 2; i += THREADS_PB) idx_sm[i] = g_idx4[ts + i];
    __syncthreads();

    int g = WARPS_PB * tb + w;             // global warp id (column group)
    // this lane's 4 stream columns start at real col (124g - 4 + 4l) mod D
    int v = 124 * g - 4 + 4 * l;
    if (v < 0) v += D_DIM;
    if (v >= D_DIM) v -= D_DIM;
    int kw0 = *(const int*)(g_keys01 + 0 * D_DIM + v);
    int kw1 = *(const int*)(g_keys01 + 1 * D_DIM + v);
    int kw2 = *(const int*)(g_keys01 + 2 * D_DIM + v);
    int kw3 = *(const int*)(g_keys01 + 3 * D_DIM + v);

    const unsigned char* lp = lw_sm + (ofs + 124 * w + 4 * l);

    int p1[4], p2[4], cur[4];
    int acc[4] = {0, 0, 0, 0};
    load_u(lp, idx_sm[0], kw0, kw1, kw2, kw3, p2);   // u(ts)
    load_u(lp, idx_sm[1], kw0, kw1, kw2, kw3, p1);   // u(ts+1)

    #pragma unroll 3
    for (int i = 2; i < nt + 2; i++) {
        load_u(lp, idx_sm[i], kw0, kw1, kw2, kw3, cur);   // u(ts+i)
        // emit term(ts+i-2): u_{c-2}(t) * u_{c-1}(t+1) * u_c(t+2)
        int a0 = __shfl_up_sync(0xffffffffu, p2[2], 1);
        int a1 = __shfl_up_sync(0xffffffffu, p2[3], 1);
        int b0 = __shfl_up_sync(0xffffffffu, p1[3], 1);
        acc[0] += a0    * b0    * cur[0];
        acc[1] += a1    * p1[0] * cur[1];
        acc[2] += p2[0] * p1[1] * cur[2];
        acc[3] += p2[1] * p1[2] * cur[3];
        p2[0] = p1[0]; p2[1] = p1[1]; p2[2] = p1[2]; p2[3] = p1[3];
        p1[0] = cur[0]; p1[1] = cur[1]; p1[2] = cur[2]; p1[3] = cur[3];
    }

    if (l >= 1) {                           // lane 0 is halo-only
        int obase = 124 * g + 4 * (l - 1);
        int* prow = g_partial + s * PART_STRIDE;
        #pragma unroll
        for (int j = 0; j < 4; j++) {
            int oc = obase + j;
            if (oc < D_DIM) prow[oc] = acc[j];   // deterministic private slot
        }
    }
}

// ---------------- final reduce + quantize (coalesced, ~1.1MB traffic) ----------------
__global__ __launch_bounds__(128) void k_final(float* __restrict__ out) {
    int d = blockIdx.x * 128 + threadIdx.x;
    if (d >= D_DIM) return;
    int sum = 0;
    #pragma unroll
    for (int c = 0; c < NCHUNK; c++) sum += g_partial[c * PART_STRIDE + d];
    float sample = -8.0f * (float)sum;      // exact: |.| < 2^24
    float x = sample * g_comb[d];
    out[d] = (x > 0.0f) ? 1.0f : -1.0f;
}

// ---------------- launch ----------------
extern "C" void kernel_launch(void* const* d_in, const int* in_sizes, int n_in,
                              void* d_out, int out_size) {
    const float* signals = (const float*)d_in[0];
    const float* feat    = (const float*)d_in[1];
    const float* keys_hv = (const float*)d_in[2];
    const float* lw      = (const float*)d_in[3];
    const float* feat_w  = (const float*)d_in[4];
    const float* feat_b  = (const float*)d_in[5];
    const float* mfcc_w  = (const float*)d_in[6];
    const float* mfcc_b  = (const float*)d_in[7];
    float* out = (float*)d_out;

    k_pre   <<<COMB_BLOCKS + PREP_BLOCKS, COMB_TPB>>>(signals, keys_hv, lw,
                                                      feat, feat_w, feat_b, mfcc_w, mfcc_b);
    k_main  <<<dim3(NTILE, NCHUNK), THREADS_PB>>>();
    k_final <<<COMB_BLOCKS, 128>>>(out);
}

// round 7
// speedup vs baseline: 2.0068x; 1.7168x over previous
#include <cuda_runtime.h>
#include <math.h>

#define D_DIM   10000
#define LVL     100
#define T_STEPS 2048
#define TERMS   2046          // T - 3 + 1
#define NCHUNK  27
#define TCHUNK  76            // 27*76 = 2052 >= 2046
#define NTILE   27            // 81 warps / 3 warps-per-block
#define TILE_W  400           // padded level-tile width (bytes)
#define WARPS_PB 3
#define THREADS_PB 96
#define EXT_W   10512         // D + 512, circularly extended & shifted by 4; %16==0
#define PART_STRIDE 10048
#define CB_D    64            // d-tile per comb block
#define CB_TPB  128
#define CB_X    157           // ceil(10000/64)
#define PREP_TPB 128
#define PREP_ELEMS (LVL * EXT_W)             // 1051200
#define PREP_BLOCKS ((PREP_ELEMS / 4 + PREP_TPB - 1) / PREP_TPB)

// ---------------- scratch (static device globals; no allocation) ----------------
__device__ unsigned char g_lwext[LVL * EXT_W];     // ext[row][j] = (LW[row][(j-4) mod D] > 0)
__device__ unsigned char g_keys01[4 * D_DIM];      // (keys_hv > 0)
__device__ int4          g_idx4[T_STEPS];          // per-t levels, pre-scaled by TILE_W
__device__ int           g_partial[NCHUNK * PART_STRIDE];
__device__ float         g_hsum[D_DIM];            // 29-h combination (no mfcc)
__device__ float         g_mp0[D_DIM];             // prod of mfcc k=0..2
__device__ float         g_mp1[D_DIM];             // prod of mfcc k=3..5

__constant__ int c_CF[29] = {547,548,549,551,554,556,557,558,559,560,561,562,563,565,
                             566,567,570,576,580,581,582,583,584,585,588,593,598,599,600};

// ---------------- prep kernel (lean) ----------------
__device__ __forceinline__ int level_of(float x) {
    x = fminf(fmaxf(x, 0.0f), 1.0f);
    float r = rintf(x * 99.0f);          // round-half-to-even, matches jnp.round
    int i = (int)r;
    i = i < 0 ? 0 : (i > 99 ? 99 : i);
    return i;
}

__global__ __launch_bounds__(PREP_TPB) void k_prep(
        const float* __restrict__ signals,
        const float* __restrict__ keys,
        const float* __restrict__ lw) {
    int gi = blockIdx.x * PREP_TPB + threadIdx.x;
    int e0 = 4 * gi;
    if (e0 < PREP_ELEMS) {
        int row  = e0 / EXT_W;
        int col0 = e0 - row * EXT_W;          // EXT_W%4==0 so all 4 in same row
        uchar4 v;
        unsigned char* pv = (unsigned char*)&v;
        #pragma unroll
        for (int j = 0; j < 4; j++) {
            int src = col0 + j - 4;
            if (src < 0) src += D_DIM;
            else if (src >= D_DIM) src -= D_DIM;
            pv[j] = (lw[row * D_DIM + src] > 0.0f) ? 1 : 0;
        }
        *(uchar4*)(g_lwext + e0) = v;
    }
    if (gi < D_DIM) {                          // keys: 4*D bytes
        uchar4 v;
        unsigned char* pv = (unsigned char*)&v;
        #pragma unroll
        for (int j = 0; j < 4; j++) pv[j] = (keys[e0 + j] > 0.0f) ? 1 : 0;
        *(uchar4*)(g_keys01 + e0) = v;
    }
    if (gi < T_STEPS) {
        float4 sg = ((const float4*)signals)[gi];
        g_idx4[gi] = make_int4(level_of(sg.x) * TILE_W, level_of(sg.y) * TILE_W,
                               level_of(sg.z) * TILE_W, level_of(sg.w) * TILE_W);
    }
}

// ---------------- comb kernel: grid (157, 2); 64 d's per block, 3 k's per y ----------------
__global__ __launch_bounds__(CB_TPB) void k_comb(
        const float* __restrict__ feat,
        const float* __restrict__ feat_w,
        const float* __restrict__ feat_b,
        const float* __restrict__ mfcc_w,
        const float* __restrict__ mfcc_b) {
    __shared__ __align__(16) float wtile[CB_D * 91];   // 23296 B
    __shared__ float feat_s[600];
    __shared__ float p_sm[3][CB_D];

    int tid = threadIdx.x;
    int x = blockIdx.x, y = blockIdx.y;
    int d0 = x * CB_D;
    int rows = D_DIM - d0; if (rows > CB_D) rows = CB_D;
    int nInt4 = (rows * 91) >> 2;                      // rows*91 divisible by 4

    for (int i = tid; i < 600; i += CB_TPB) feat_s[i] = feat[i];

    int pr   = tid >> 1;          // pair index = local d
    int half = tid & 1;
    int f0 = half ? 48 : 0;
    int f1 = half ? 91 : 48;

    #pragma unroll
    for (int kk = 0; kk < 3; kk++) {
        int k = 3 * y + kk;
        __syncthreads();
        const int4* src = (const int4*)(mfcc_w + ((size_t)(k * D_DIM + d0)) * 91);
        for (int i = tid; i < nInt4; i += CB_TPB) ((int4*)wtile)[i] = src[i];
        __syncthreads();
        if (pr < rows) {
            const float* row = wtile + pr * 91;
            const float* fr  = feat_s + k * 91;
            float s = 0.0f;
            #pragma unroll
            for (int f = f0; f < f1; f++) s += row[f] * fr[f];
            s += __shfl_xor_sync(0xffffffffu, s, 1);
            if (half == 0) p_sm[kk][pr] = s;
        }
    }
    __syncthreads();

    int d = d0 + tid;
    if (tid < rows) {
        float m = 1.0f;
        #pragma unroll
        for (int kk = 0; kk < 3; kk++) {
            int k = 3 * y + kk;
            float pv = p_sm[kk][tid];
            float b  = mfcc_b[k * D_DIM + d];
            m *= cosf(pv + b) * sinf(pv);
        }
        if (y == 0) {
            g_mp0[d] = m;
            float h[29];
            #pragma unroll
            for (int j = 0; j < 29; j++) {
                float sel  = feat_s[c_CF[j] - 1];
                float wv   = feat_w[j * D_DIM + d];
                float bv   = feat_b[j * D_DIM + d];
                float proj = sel * wv;
                h[j] = cosf(proj + bv) * sinf(proj);
            }
            g_hsum[d] =
                  h[0]  * h[8]  * h[13]
                + h[1]  * h[9]  * h[14]
                + h[2]  * h[10] * h[15]
                + h[3]  * h[4]
                + h[5] * h[7] * h[22] * h[6] * h[23] * h[19] * h[18]
                       * h[20] * h[21] * h[26] * h[28] * h[27]
                + h[11] + h[12]
                + h[16] * h[24]
                + h[17] + h[25];
        } else {
            g_mp1[d] = m;
        }
    }
}

// ---------------- main n-gram kernel ----------------
// Bytewise sign algebra: b01 = (x>0); lw*key = 1-2*(bl^bk); per_t = 4-2*s, s=sum_c xor.
// With u = s-2, per_t = -2u, so ngram term = -8 * uA*uB*uC. All exact integers.
__device__ __forceinline__ void load_u(const unsigned char* lp, const int4 iq,
                                       int kw0, int kw1, int kw2, int kw3, int* u) {
    int x0 = *(const int*)(lp + iq.x) ^ kw0;
    int x1 = *(const int*)(lp + iq.y) ^ kw1;
    int x2 = *(const int*)(lp + iq.z) ^ kw2;
    int x3 = *(const int*)(lp + iq.w) ^ kw3;
    int sp = x0 + x1 + x2 + x3;       // bytewise sums, each <= 4, no carries
    u[0] = ( sp        & 0xFF) - 2;
    u[1] = ((sp >> 8 ) & 0xFF) - 2;
    u[2] = ((sp >> 16) & 0xFF) - 2;
    u[3] = ( sp >> 24        ) - 2;
}

__global__ __launch_bounds__(THREADS_PB) void k_main() {
    __shared__ unsigned char lw_sm[LVL * TILE_W];   // 40000 B
    __shared__ int4 idx_sm[TCHUNK + 2];

    int tb = blockIdx.x;     // column tile
    int s  = blockIdx.y;     // t-chunk
    int tid = threadIdx.x;
    int w = tid >> 5, l = tid & 31;

    // Load level tile, 16B vectorized (base2 aligned, ofs = skew within tile)
    int base  = 372 * tb;    // into ext array (already shifted by 4)
    int ofs   = base & 15;
    int base2 = base - ofs;
    {
        int4* dst = (int4*)lw_sm;
        #pragma unroll 4
        for (int i = tid; i < LVL * (TILE_W / 16); i += THREADS_PB) {
            int row = i / (TILE_W / 16);
            int c   = i - row * (TILE_W / 16);
            dst[i] = *(const int4*)(g_lwext + row * EXT_W + base2 + 16 * c);
        }
    }
    int ts = s * TCHUNK;
    int te = ts + TCHUNK; if (te > TERMS) te = TERMS;
    int nt = te - ts;                      // #terms this chunk (>= 1)
    for (int i = tid; i < nt + 2; i += THREADS_PB) idx_sm[i] = g_idx4[ts + i];
    __syncthreads();

    int g = WARPS_PB * tb + w;             // global warp id (column group)
    // this lane's 4 stream columns start at real col (124g - 4 + 4l) mod D
    int v = 124 * g - 4 + 4 * l;
    if (v < 0) v += D_DIM;
    if (v >= D_DIM) v -= D_DIM;
    int kw0 = *(const int*)(g_keys01 + 0 * D_DIM + v);
    int kw1 = *(const int*)(g_keys01 + 1 * D_DIM + v);
    int kw2 = *(const int*)(g_keys01 + 2 * D_DIM + v);
    int kw3 = *(const int*)(g_keys01 + 3 * D_DIM + v);

    const unsigned char* lp = lw_sm + (ofs + 124 * w + 4 * l);

    int p1[4], p2[4], cur[4];
    int acc[4] = {0, 0, 0, 0};
    load_u(lp, idx_sm[0], kw0, kw1, kw2, kw3, p2);   // u(ts)
    load_u(lp, idx_sm[1], kw0, kw1, kw2, kw3, p1);   // u(ts+1)

    #pragma unroll 3
    for (int i = 2; i < nt + 2; i++) {
        load_u(lp, idx_sm[i], kw0, kw1, kw2, kw3, cur);   // u(ts+i)
        // emit term(ts+i-2): u_{c-2}(t) * u_{c-1}(t+1) * u_c(t+2)
        int a0 = __shfl_up_sync(0xffffffffu, p2[2], 1);
        int a1 = __shfl_up_sync(0xffffffffu, p2[3], 1);
        int b0 = __shfl_up_sync(0xffffffffu, p1[3], 1);
        acc[0] += a0    * b0    * cur[0];
        acc[1] += a1    * p1[0] * cur[1];
        acc[2] += p2[0] * p1[1] * cur[2];
        acc[3] += p2[1] * p1[2] * cur[3];
        p2[0] = p1[0]; p2[1] = p1[1]; p2[2] = p1[2]; p2[3] = p1[3];
        p1[0] = cur[0]; p1[1] = cur[1]; p1[2] = cur[2]; p1[3] = cur[3];
    }

    if (l >= 1) {                           // lane 0 is halo-only
        int obase = 124 * g + 4 * (l - 1);
        int* prow = g_partial + s * PART_STRIDE;
        #pragma unroll
        for (int j = 0; j < 4; j++) {
            int oc = obase + j;
            if (oc < D_DIM) prow[oc] = acc[j];   // deterministic private slot
        }
    }
}

// ---------------- final reduce + comb assembly + quantize ----------------
__global__ __launch_bounds__(128) void k_final(float* __restrict__ out) {
    int d = blockIdx.x * 128 + threadIdx.x;
    if (d >= D_DIM) return;
    int sum = 0;
    #pragma unroll
    for (int c = 0; c < NCHUNK; c++) sum += g_partial[c * PART_STRIDE + d];
    float comb = g_hsum[d] + g_mp0[d] * g_mp1[d];
    float sample = -8.0f * (float)sum;      // exact: |.| < 2^24
    float x = sample * comb;
    out[d] = (x > 0.0f) ? 1.0f : -1.0f;
}

// ---------------- launch ----------------
extern "C" void kernel_launch(void* const* d_in, const int* in_sizes, int n_in,
                              void* d_out, int out_size) {
    const float* signals = (const float*)d_in[0];
    const float* feat    = (const float*)d_in[1];
    const float* keys_hv = (const float*)d_in[2];
    const float* lw      = (const float*)d_in[3];
    const float* feat_w  = (const float*)d_in[4];
    const float* feat_b  = (const float*)d_in[5];
    const float* mfcc_w  = (const float*)d_in[6];
    const float* mfcc_b  = (const float*)d_in[7];
    float* out = (float*)d_out;

    k_prep  <<<PREP_BLOCKS, PREP_TPB>>>(signals, keys_hv, lw);
    k_comb  <<<dim3(CB_X, 2), CB_TPB>>>(feat, feat_w, feat_b, mfcc_w, mfcc_b);
    k_main  <<<dim3(NTILE, NCHUNK), THREADS_PB>>>();
    k_final <<<(D_DIM + 127) / 128, 128>>>(out);
}

// round 9
// speedup vs baseline: 2.1377x; 1.0652x over previous
#include <cuda_runtime.h>
#include <math.h>

#define D_DIM   10000
#define LVL     100
#define T_STEPS 2048
#define TERMS   2046          // T - 3 + 1
#define NCHUNK  27
#define TCHUNK  76            // 27*76 = 2052 >= 2046
#define NTILE   27            // 81 warps / 3 warps-per-block
#define TILE_W  400           // padded level-tile width (bytes)
#define WARPS_PB 3
#define THREADS_PB 96
#define EXT_W   10512         // D + 512, circularly extended & shifted by 4; %16==0
#define PART_STRIDE 10048
#define CB_D    64            // d-tile per comb block
#define CB_TPB  128
#define CB_X    157           // ceil(10000/64)
#define COMB_BLOCKS (CB_X * 2)               // 314
#define PREP_ELEMS (LVL * EXT_W)             // 1051200
#define PREP_BLOCKS ((PREP_ELEMS / 4 + CB_TPB - 1) / CB_TPB)   // 2054

// ---------------- scratch (static device globals; no allocation) ----------------
__device__ unsigned char g_lwext[LVL * EXT_W];     // ext[row][j] = (LW[row][(j-4) mod D] > 0)
__device__ unsigned char g_keys01[4 * D_DIM];      // (keys_hv > 0)
__device__ int4          g_idx4[T_STEPS];          // per-t levels, pre-scaled by TILE_W
__device__ int           g_partial[NCHUNK * PART_STRIDE];
__device__ float         g_hsum[D_DIM];            // 29-h combination (no mfcc)
__device__ float         g_mp0[D_DIM];             // prod of mfcc k=0..2
__device__ float         g_mp1[D_DIM];             // prod of mfcc k=3..5

__constant__ int c_CF[29] = {547,548,549,551,554,556,557,558,559,560,561,562,563,565,
                             566,567,570,576,580,581,582,583,584,585,588,593,598,599,600};

// ---------------- merged pre kernel: comb blocks first, prep blocks after ----------------
__device__ __forceinline__ int level_of(float x) {
    x = fminf(fmaxf(x, 0.0f), 1.0f);
    float r = rintf(x * 99.0f);          // round-half-to-even, matches jnp.round
    int i = (int)r;
    i = i < 0 ? 0 : (i > 99 ? 99 : i);
    return i;
}

__global__ __launch_bounds__(CB_TPB) void k_pre(
        const float* __restrict__ signals,
        const float* __restrict__ keys,
        const float* __restrict__ lw,
        const float* __restrict__ feat,
        const float* __restrict__ feat_w,
        const float* __restrict__ feat_b,
        const float* __restrict__ mfcc_w,
        const float* __restrict__ mfcc_b) {
    __shared__ __align__(16) float wtile[CB_D * 91];   // 23296 B
    __shared__ float feat_s[600];
    __shared__ float p_sm[3][CB_D];

    int tid = threadIdx.x;
    int b = blockIdx.x;
    if (b < COMB_BLOCKS) {
        // ---- comb: 64 d's per block, 3 k's per y-half, thread-pairs split rows ----
        int x = b >> 1, y = b & 1;
        int d0 = x * CB_D;
        int rows = D_DIM - d0; if (rows > CB_D) rows = CB_D;
        int nInt4 = (rows * 91) >> 2;                  // rows*91 divisible by 4

        for (int i = tid; i < 600; i += CB_TPB) feat_s[i] = feat[i];

        int pr   = tid >> 1;          // pair index = local d
        int half = tid & 1;
        int f0 = half ? 48 : 0;
        int f1 = half ? 91 : 48;

        #pragma unroll
        for (int kk = 0; kk < 3; kk++) {
            int k = 3 * y + kk;
            __syncthreads();
            const int4* src = (const int4*)(mfcc_w + ((size_t)(k * D_DIM + d0)) * 91);
            for (int i = tid; i < nInt4; i += CB_TPB) ((int4*)wtile)[i] = src[i];
            __syncthreads();
            if (pr < rows) {
                const float* row = wtile + pr * 91;
                const float* fr  = feat_s + k * 91;
                float s = 0.0f;
                #pragma unroll
                for (int f = f0; f < f1; f++) s += row[f] * fr[f];
                s += __shfl_xor_sync(0xffffffffu, s, 1);
                if (half == 0) p_sm[kk][pr] = s;
            }
        }
        __syncthreads();

        int d = d0 + tid;
        if (tid < rows) {
            float m = 1.0f;
            #pragma unroll
            for (int kk = 0; kk < 3; kk++) {
                int k = 3 * y + kk;
                float pv = p_sm[kk][tid];
                float bb = mfcc_b[k * D_DIM + d];
                m *= cosf(pv + bb) * sinf(pv);
            }
            if (y == 0) {
                g_mp0[d] = m;
                float h[29];
                #pragma unroll
                for (int j = 0; j < 29; j++) {
                    float sel  = feat_s[c_CF[j] - 1];
                    float wv   = feat_w[j * D_DIM + d];
                    float bv   = feat_b[j * D_DIM + d];
                    float proj = sel * wv;
                    h[j] = cosf(proj + bv) * sinf(proj);
                }
                g_hsum[d] =
                      h[0]  * h[8]  * h[13]
                    + h[1]  * h[9]  * h[14]
                    + h[2]  * h[10] * h[15]
                    + h[3]  * h[4]
                    + h[5] * h[7] * h[22] * h[6] * h[23] * h[19] * h[18]
                           * h[20] * h[21] * h[26] * h[28] * h[27]
                    + h[11] + h[12]
                    + h[16] * h[24]
                    + h[17] + h[25];
            } else {
                g_mp1[d] = m;
            }
        }
    } else {
        // ---- prep: 4 elements per thread ----
        int gi = (b - COMB_BLOCKS) * CB_TPB + tid;
        int e0 = 4 * gi;
        if (e0 < PREP_ELEMS) {
            int row  = e0 / EXT_W;
            int col0 = e0 - row * EXT_W;          // EXT_W%4==0 so all 4 in same row
            uchar4 v;
            unsigned char* pv = (unsigned char*)&v;
            #pragma unroll
            for (int j = 0; j < 4; j++) {
                int src = col0 + j - 4;
                if (src < 0) src += D_DIM;
                else if (src >= D_DIM) src -= D_DIM;
                pv[j] = (lw[row * D_DIM + src] > 0.0f) ? 1 : 0;
            }
            *(uchar4*)(g_lwext + e0) = v;
        }
        if (gi < D_DIM) {                          // keys: 4*D bytes
            uchar4 v;
            unsigned char* pv = (unsigned char*)&v;
            #pragma unroll
            for (int j = 0; j < 4; j++) pv[j] = (keys[e0 + j] > 0.0f) ? 1 : 0;
            *(uchar4*)(g_keys01 + e0) = v;
        }
        if (gi < T_STEPS) {
            float4 sg = ((const float4*)signals)[gi];
            g_idx4[gi] = make_int4(level_of(sg.x) * TILE_W, level_of(sg.y) * TILE_W,
                                   level_of(sg.z) * TILE_W, level_of(sg.w) * TILE_W);
        }
    }
}

// ---------------- main n-gram kernel ----------------
// Bytewise sign algebra: b01 = (x>0); lw*key = 1-2*(bl^bk); per_t = 4-2*s, s=sum_c xor.
// With u = s-2, per_t = -2u, so ngram term = -8 * uA*uB*uC. All exact integers.
__device__ __forceinline__ void load_u(const unsigned char* lp, const int4 iq,
                                       int kw0, int kw1, int kw2, int kw3, int* u) {
    int x0 = *(const int*)(lp + iq.x) ^ kw0;
    int x1 = *(const int*)(lp + iq.y) ^ kw1;
    int x2 = *(const int*)(lp + iq.z) ^ kw2;
    int x3 = *(const int*)(lp + iq.w) ^ kw3;
    int sp = x0 + x1 + x2 + x3;       // bytewise sums, each <= 4, no carries
    u[0] = ( sp        & 0xFF) - 2;
    u[1] = ((sp >> 8 ) & 0xFF) - 2;
    u[2] = ((sp >> 16) & 0xFF) - 2;
    u[3] = ( sp >> 24        ) - 2;
}

__global__ __launch_bounds__(THREADS_PB) void k_main() {
    __shared__ unsigned char lw_sm[LVL * TILE_W];   // 40000 B
    __shared__ int4 idx_sm[TCHUNK + 2];

    int tb = blockIdx.x;     // column tile
    int s  = blockIdx.y;     // t-chunk
    int tid = threadIdx.x;
    int w = tid >> 5, l = tid & 31;

    // Load level tile, 16B vectorized (base2 aligned, ofs = skew within tile)
    int base  = 372 * tb;    // into ext array (already shifted by 4)
    int ofs   = base & 15;
    int base2 = base - ofs;
    {
        int4* dst = (int4*)lw_sm;
        #pragma unroll 4
        for (int i = tid; i < LVL * (TILE_W / 16); i += THREADS_PB) {
            int row = i / (TILE_W / 16);
            int c   = i - row * (TILE_W / 16);
            dst[i] = *(const int4*)(g_lwext + row * EXT_W + base2 + 16 * c);
        }
    }
    int ts = s * TCHUNK;
    int te = ts + TCHUNK; if (te > TERMS) te = TERMS;
    int nt = te - ts;                      // #terms this chunk (>= 1)
    for (int i = tid; i < nt + 2; i += THREADS_PB) idx_sm[i] = g_idx4[ts + i];
    __syncthreads();

    int g = WARPS_PB * tb + w;             // global warp id (column group)
    // this lane's 4 stream columns start at real col (124g - 4 + 4l) mod D
    int v = 124 * g - 4 + 4 * l;
    if (v < 0) v += D_DIM;
    if (v >= D_DIM) v -= D_DIM;
    int kw0 = *(const int*)(g_keys01 + 0 * D_DIM + v);
    int kw1 = *(const int*)(g_keys01 + 1 * D_DIM + v);
    int kw2 = *(const int*)(g_keys01 + 2 * D_DIM + v);
    int kw3 = *(const int*)(g_keys01 + 3 * D_DIM + v);

    const unsigned char* lp = lw_sm + (ofs + 124 * w + 4 * l);

    int p1[4], p2[4], cur[4];
    int acc[4] = {0, 0, 0, 0};
    load_u(lp, idx_sm[0], kw0, kw1, kw2, kw3, p2);   // u(ts)
    load_u(lp, idx_sm[1], kw0, kw1, kw2, kw3, p1);   // u(ts+1)

    #pragma unroll 3
    for (int i = 2; i < nt + 2; i++) {
        load_u(lp, idx_sm[i], kw0, kw1, kw2, kw3, cur);   // u(ts+i)
        // emit term(ts+i-2): u_{c-2}(t) * u_{c-1}(t+1) * u_c(t+2)
        int a0 = __shfl_up_sync(0xffffffffu, p2[2], 1);
        int a1 = __shfl_up_sync(0xffffffffu, p2[3], 1);
        int b0 = __shfl_up_sync(0xffffffffu, p1[3], 1);
        acc[0] += a0    * b0    * cur[0];
        acc[1] += a1    * p1[0] * cur[1];
        acc[2] += p2[0] * p1[1] * cur[2];
        acc[3] += p2[1] * p1[2] * cur[3];
        p2[0] = p1[0]; p2[1] = p1[1]; p2[2] = p1[2]; p2[3] = p1[3];
        p1[0] = cur[0]; p1[1] = cur[1]; p1[2] = cur[2]; p1[3] = cur[3];
    }

    if (l >= 1) {                           // lane 0 is halo-only
        int obase = 124 * g + 4 * (l - 1);
        int* prow = g_partial + s * PART_STRIDE;
        #pragma unroll
        for (int j = 0; j < 4; j++) {
            int oc = obase + j;
            if (oc < D_DIM) prow[oc] = acc[j];   // deterministic private slot
        }
    }
}

// ---------------- final reduce + comb assembly + quantize ----------------
// grid 157 x 256: 64 d's per block, 4 threads per d (7/7/7/6 chunks), smem combine.
__global__ __launch_bounds__(256) void k_final(float* __restrict__ out) {
    __shared__ int s_red[4][64];
    int tid = threadIdx.x;
    int q  = tid >> 6;           // chunk quarter 0..3
    int dl = tid & 63;
    int d  = blockIdx.x * 64 + dl;

    int sum = 0;
    if (d < D_DIM) {
        int c0 = q * 7;
        int nc = (q < 3) ? 7 : 6;
        #pragma unroll 7
        for (int c = 0; c < 7; c++) {
            if (c < nc) sum += g_partial[(c0 + c) * PART_STRIDE + d];
        }
    }
    s_red[q][dl] = sum;
    __syncthreads();
    if (tid < 64 && d < D_DIM) {
        int total = s_red[0][dl] + s_red[1][dl] + s_red[2][dl] + s_red[3][dl];
        float comb = g_hsum[d] + g_mp0[d] * g_mp1[d];
        float sample = -8.0f * (float)total;   // exact: |.| < 2^24
        float x = sample * comb;
        out[d] = (x > 0.0f) ? 1.0f : -1.0f;
    }
}

// ---------------- launch ----------------
extern "C" void kernel_launch(void* const* d_in, const int* in_sizes, int n_in,
                              void* d_out, int out_size) {
    const float* signals = (const float*)d_in[0];
    const float* feat    = (const float*)d_in[1];
    const float* keys_hv = (const float*)d_in[2];
    const float* lw      = (const float*)d_in[3];
    const float* feat_w  = (const float*)d_in[4];
    const float* feat_b  = (const float*)d_in[5];
    const float* mfcc_w  = (const float*)d_in[6];
    const float* mfcc_b  = (const float*)d_in[7];
    float* out = (float*)d_out;

    k_pre   <<<COMB_BLOCKS + PREP_BLOCKS, CB_TPB>>>(signals, keys_hv, lw,
                                                    feat, feat_w, feat_b, mfcc_w, mfcc_b);
    k_main  <<<dim3(NTILE, NCHUNK), THREADS_PB>>>();
    k_final <<<CB_X, 256>>>(out);
}

// round 17
// speedup vs baseline: 2.4180x; 1.1311x over previous
#include <cuda_runtime.h>
#include <math.h>

#define D_DIM   10000
#define LVL     100
#define T_STEPS 2048
#define TERMS   2046          // T - 3 + 1
#define NCHUNK  27
#define TCHUNK  76            // 27*76 = 2052 >= 2046 (last chunk: 70 terms)
#define NROWS   (NCHUNK * 2)  // 54 partial rows (each chunk split in two halves)
#define NTILE   27            // 81 column-warp-groups / 3 per block
#define TILE_W  400           // padded level-tile width (bytes)
#define THREADS_PB 192        // 6 warps: 3 column groups x 2 time halves
#define EXT_W   10512         // D + 512, circularly extended & shifted by 4; %16==0
#define PART_STRIDE 10048
#define CB_D    64            // d-tile per mfcc block
#define CB_TPB  128
#define CB_X    157           // ceil(10000/64)
#define NB_M    (CB_X * 6)    // 942 mfcc blocks
#define NB_H    79            // h blocks (128 d each)
#define PREP_ELEMS (LVL * EXT_W)             // 1051200
#define PREP_BLOCKS ((PREP_ELEMS / 4 + CB_TPB - 1) / CB_TPB)   // 2054

// ---------------- scratch (static device globals; no allocation) ----------------
__device__ unsigned char g_lwext[LVL * EXT_W];     // ext[row][j] = (LW[row][(j-4) mod D] > 0)
__device__ unsigned char g_keys01[4 * D_DIM];      // (keys_hv > 0)
__device__ int4          g_idx4[T_STEPS];          // per-t levels, pre-scaled by TILE_W
__device__ int           g_partial[NROWS * PART_STRIDE];
__device__ float         g_hsum[D_DIM];            // 29-h combination (no mfcc)
__device__ float         g_mk[6 * D_DIM];          // per-k mfcc HVs

__constant__ int c_CF[29] = {547,548,549,551,554,556,557,558,559,560,561,562,563,565,
                             566,567,570,576,580,581,582,583,584,585,588,593,598,599,600};

// ---------------- merged pre kernel: mfcc blocks, h blocks, prep blocks ----------------
__device__ __forceinline__ int level_of(float x) {
    x = fminf(fmaxf(x, 0.0f), 1.0f);
    float r = rintf(x * 99.0f);          // round-half-to-even, matches jnp.round
    int i = (int)r;
    i = i < 0 ? 0 : (i > 99 ? 99 : i);
    return i;
}

__global__ __launch_bounds__(CB_TPB) void k_pre(
        const float* __restrict__ signals,
        const float* __restrict__ keys,
        const float* __restrict__ lw,
        const float* __restrict__ feat,
        const float* __restrict__ feat_w,
        const float* __restrict__ feat_b,
        const float* __restrict__ mfcc_w,
        const float* __restrict__ mfcc_b) {
    __shared__ __align__(16) float wtile[CB_D * 91];   // 23296 B
    __shared__ float feat_s[91];
    __shared__ float p_sm[CB_D];

    int tid = threadIdx.x;
    int b = blockIdx.x;
    if (b < NB_M) {
        // ---- one (k, 64-d tile) per block ----
        int x = b / 6, k = b - 6 * x;
        int d0 = x * CB_D;
        int rows = D_DIM - d0; if (rows > CB_D) rows = CB_D;
        int nInt4 = (rows * 91) >> 2;                  // rows*91 divisible by 4

        for (int i = tid; i < 91; i += CB_TPB) feat_s[i] = feat[k * 91 + i];
        const int4* src = (const int4*)(mfcc_w + ((size_t)(k * D_DIM + d0)) * 91);
        for (int i = tid; i < nInt4; i += CB_TPB) ((int4*)wtile)[i] = src[i];
        __syncthreads();

        int pr   = tid >> 1;          // pair index = local d
        int half = tid & 1;
        if (pr < rows) {
            const float* row = wtile + pr * 91;
            float s = 0.0f;
            if (half == 0) {
                for (int f = 0; f < 48; f++) s += row[f] * feat_s[f];
            } else {
                for (int f = 48; f < 91; f++) s += row[f] * feat_s[f];
            }
            s += __shfl_xor_sync(0xffffffffu, s, 1);
            if (half == 0) p_sm[pr] = s;
        }
        __syncthreads();
        if (tid < rows) {
            int d = d0 + tid;
            float pv = p_sm[tid];
            float bb = mfcc_b[k * D_DIM + d];
            g_mk[k * D_DIM + d] = cosf(pv + bb) * sinf(pv);
        }
    } else if (b < NB_M + NB_H) {
        // ---- h block: 128 d's ----
        int d = (b - NB_M) * 128 + tid;
        if (d < D_DIM) {
            float h[29];
            #pragma unroll
            for (int j = 0; j < 29; j++) {
                float sel  = feat[c_CF[j] - 1];
                float wv   = feat_w[j * D_DIM + d];
                float bv   = feat_b[j * D_DIM + d];
                float proj = sel * wv;
                h[j] = cosf(proj + bv) * sinf(proj);
            }
            g_hsum[d] =
                  h[0]  * h[8]  * h[13]
                + h[1]  * h[9]  * h[14]
                + h[2]  * h[10] * h[15]
                + h[3]  * h[4]
                + h[5] * h[7] * h[22] * h[6] * h[23] * h[19] * h[18]
                       * h[20] * h[21] * h[26] * h[28] * h[27]
                + h[11] + h[12]
                + h[16] * h[24]
                + h[17] + h[25];
        }
    } else {
        // ---- prep: 4 elements per thread ----
        int gi = (b - NB_M - NB_H) * CB_TPB + tid;
        int e0 = 4 * gi;
        if (e0 < PREP_ELEMS) {
            int row  = e0 / EXT_W;
            int col0 = e0 - row * EXT_W;          // EXT_W%4==0 so all 4 in same row
            uchar4 v;
            unsigned char* pv = (unsigned char*)&v;
            #pragma unroll
            for (int j = 0; j < 4; j++) {
                int src = col0 + j - 4;
                if (src < 0) src += D_DIM;
                else if (src >= D_DIM) src -= D_DIM;
                pv[j] = (lw[row * D_DIM + src] > 0.0f) ? 1 : 0;
            }
            *(uchar4*)(g_lwext + e0) = v;
        }
        if (gi < D_DIM) {                          // keys: 4*D bytes
            uchar4 v;
            unsigned char* pv = (unsigned char*)&v;
            #pragma unroll
            for (int j = 0; j < 4; j++) pv[j] = (keys[e0 + j] > 0.0f) ? 1 : 0;
            *(uchar4*)(g_keys01 + e0) = v;
        }
        if (gi < T_STEPS) {
            float4 sg = ((const float4*)signals)[gi];
            g_idx4[gi] = make_int4(level_of(sg.x) * TILE_W, level_of(sg.y) * TILE_W,
                                   level_of(sg.z) * TILE_W, level_of(sg.w) * TILE_W);
        }
    }
}

// ---------------- main n-gram kernel ----------------
// Bytewise sign algebra: b01 = (x>0); lw*key = 1-2*(bl^bk); per_t = 4-2*s, s=sum_c xor.
// With u = s-2, per_t = -2u, so ngram term = -8 * uA*uB*uC. All exact integers.
__device__ __forceinline__ void load_u(const unsigned char* lp, const int4 iq,
                                       int kw0, int kw1, int kw2, int kw3, int* u) {
    int x0 = *(const int*)(lp + iq.x) ^ kw0;
    int x1 = *(const int*)(lp + iq.y) ^ kw1;
    int x2 = *(const int*)(lp + iq.z) ^ kw2;
    int x3 = *(const int*)(lp + iq.w) ^ kw3;
    int sp = x0 + x1 + x2 + x3;       // bytewise sums, each <= 4, no carries
    u[0] = ( sp        & 0xFF) - 2;
    u[1] = ((sp >> 8 ) & 0xFF) - 2;
    u[2] = ((sp >> 16) & 0xFF) - 2;
    u[3] = ( sp >> 24        ) - 2;
}

__global__ __launch_bounds__(THREADS_PB) void k_main() {
    __shared__ unsigned char lw_sm[LVL * TILE_W];   // 40000 B
    __shared__ int4 idx_sm[TCHUNK + 2];

    int tb = blockIdx.x;     // column tile
    int s  = blockIdx.y;     // t-chunk
    int tid = threadIdx.x;
    int w = tid >> 5, l = tid & 31;
    int wh = w / 3;          // time half 0/1
    int wc = w - 3 * wh;     // column group 0..2

    // Load level tile, 16B vectorized (base2 aligned, ofs = skew within tile)
    int base  = 372 * tb;    // into ext array (already shifted by 4)
    int ofs   = base & 15;
    int base2 = base - ofs;
    {
        int4* dst = (int4*)lw_sm;
        #pragma unroll 4
        for (int i = tid; i < LVL * (TILE_W / 16); i += THREADS_PB) {
            int row = i / (TILE_W / 16);
            int c   = i - row * (TILE_W / 16);
            dst[i] = *(const int4*)(g_lwext + row * EXT_W + base2 + 16 * c);
        }
    }
    int ts = s * TCHUNK;
    int te = ts + TCHUNK; if (te > TERMS) te = TERMS;
    int nt = te - ts;                      // 76, or 70 for last chunk
    for (int i = tid; i < nt + 2; i += THREADS_PB) idx_sm[i] = g_idx4[ts + i];
    __syncthreads();

    int g = 3 * tb + wc;                   // global column-warp-group id
    // this warp-group's 4 stream columns start at real col (124g - 4 + 4l) mod D
    int v = 124 * g - 4 + 4 * l;
    if (v < 0) v += D_DIM;
    if (v >= D_DIM) v -= D_DIM;
    int kw0 = *(const int*)(g_keys01 + 0 * D_DIM + v);
    int kw1 = *(const int*)(g_keys01 + 1 * D_DIM + v);
    int kw2 = *(const int*)(g_keys01 + 2 * D_DIM + v);
    int kw3 = *(const int*)(g_keys01 + 3 * D_DIM + v);

    const unsigned char* lp = lw_sm + (ofs + 124 * wc + 4 * l);

    // time split: half 0 -> terms [0,38), half 1 -> [38,nt)  (nt>=70 so >=32 terms)
    int i0 = wh * 38;
    int i1 = wh ? nt : 38;

    int p1[4], p2[4], cur[4];
    int acc[4] = {0, 0, 0, 0};
    load_u(lp, idx_sm[i0],     kw0, kw1, kw2, kw3, p2);
    load_u(lp, idx_sm[i0 + 1], kw0, kw1, kw2, kw3, p1);

    #pragma unroll 3
    for (int i = i0 + 2; i < i1 + 2; i++) {
        load_u(lp, idx_sm[i], kw0, kw1, kw2, kw3, cur);
        // emit term(ts+i-2): u_{c-2}(t) * u_{c-1}(t+1) * u_c(t+2)
        int a0 = __shfl_up_sync(0xffffffffu, p2[2], 1);
        int a1 = __shfl_up_sync(0xffffffffu, p2[3], 1);
        int b0 = __shfl_up_sync(0xffffffffu, p1[3], 1);
        acc[0] += a0    * b0    * cur[0];
        acc[1] += a1    * p1[0] * cur[1];
        acc[2] += p2[0] * p1[1] * cur[2];
        acc[3] += p2[1] * p1[2] * cur[3];
        p2[0] = p1[0]; p2[1] = p1[1]; p2[2] = p1[2]; p2[3] = p1[3];
        p1[0] = cur[0]; p1[1] = cur[1]; p1[2] = cur[2]; p1[3] = cur[3];
    }

    if (l >= 1) {                           // lane 0 is halo-only
        int obase = 124 * g + 4 * (l - 1);
        int* prow = g_partial + (2 * s + wh) * PART_STRIDE;
        #pragma unroll
        for (int j = 0; j < 4; j++) {
            int oc = obase + j;
            if (oc < D_DIM) prow[oc] = acc[j];   // deterministic private slot
        }
    }
}

// ---------------- final reduce + comb assembly + quantize ----------------
// grid 157 x 256: 64 d's per block, 4 threads per d (14/14/14/12 chunks), smem combine.
__global__ __launch_bounds__(256) void k_final(float* __restrict__ out) {
    __shared__ int s_red[4][64];
    int tid = threadIdx.x;
    int q  = tid >> 6;           // quarter 0..3
    int dl = tid & 63;
    int d  = blockIdx.x * 64 + dl;

    int sum = 0;
    if (d < D_DIM) {
        int c0 = q * 14;
        int nc = (q < 3) ? 14 : 12;
        #pragma unroll 14
        for (int c = 0; c < 14; c++) {
            if (c < nc) sum += g_partial[(c0 + c) * PART_STRIDE + d];
        }
    }
    s_red[q][dl] = sum;
    __syncthreads();
    if (tid < 64 && d < D_DIM) {
        int total = s_red[0][dl] + s_red[1][dl] + s_red[2][dl] + s_red[3][dl];
        float m = g_mk[d];
        #pragma unroll
        for (int k = 1; k < 6; k++) m *= g_mk[k * D_DIM + d];
        float comb = g_hsum[d] + m;
        float sample = -8.0f * (float)total;   // exact: |.| < 2^24
        float x = sample * comb;
        out[d] = (x > 0.0f) ? 1.0f : -1.0f;
    }
}

// ---------------- launch ----------------
extern "C" void kernel_launch(void* const* d_in, const int* in_sizes, int n_in,
                              void* d_out, int out_size) {
    const float* signals = (const float*)d_in[0];
    const float* feat    = (const float*)d_in[1];
    const float* keys_hv = (const float*)d_in[2];
    const float* lw      = (const float*)d_in[3];
    const float* feat_w  = (const float*)d_in[4];
    const float* feat_b  = (const float*)d_in[5];
    const float* mfcc_w  = (const float*)d_in[6];
    const float* mfcc_b  = (const float*)d_in[7];
    float* out = (float*)d_out;

    k_pre   <<<NB_M + NB_H + PREP_BLOCKS, CB_TPB>>>(signals, keys_hv, lw,
                                                    feat, feat_w, feat_b, mfcc_w, mfcc_b);
    k_main  <<<dim3(NTILE, NCHUNK), THREADS_PB>>>();
    k_final <<<CB_X, 256>>>(out);
}